// round 16
// baseline (speedup 1.0000x reference)
#include <cuda_runtime.h>
#include <cfloat>

#define PH 7
#define PW 7
#define NN 4
#define CC 128
#define HH 50
#define WW 50
#define SCALE 0.0625f

// channel-last features [N][H][W][C], 5.12 MB
__device__ float g_featT[NN * HH * WW * CC];

// transpose [C,W] -> [W,C] per (b,h,c-half)
__global__ void transpose_kernel(const float* __restrict__ feat) {
    int blk = blockIdx.x;
    int b    = blk / (HH * 2);
    int rest = blk % (HH * 2);
    int h    = rest >> 1;
    int c0   = (rest & 1) * 64;

    __shared__ float tile[64 * WW];

    const float* src = feat + ((long)b * CC + c0) * (HH * WW) + h * WW;
    for (int i = threadIdx.x; i < 64 * 25; i += blockDim.x) {
        int c  = i / 25;
        int w2 = i % 25;
        float2 v = *reinterpret_cast<const float2*>(src + (long)c * (HH * WW) + w2 * 2);
        tile[c * WW + w2 * 2]     = v.x;
        tile[c * WW + w2 * 2 + 1] = v.y;
    }
    __syncthreads();
    float* dst = g_featT + ((long)(b * HH + h) * WW) * CC + c0;
    for (int i = threadIdx.x; i < 64 * WW; i += blockDim.x) {
        int w = i >> 6;
        int c = i & 63;
        dst[(long)w * CC + c] = tile[c * WW + w];
    }
}

__device__ __forceinline__ float4 fmax4(float4 a, float4 b) {
    return make_float4(fmaxf(a.x, b.x), fmaxf(a.y, b.y),
                       fmaxf(a.z, b.z), fmaxf(a.w, b.w));
}

// One block (512 thr) per ROI k. Loops ph internally; accumulates the whole
// [C][PH][PW] output tile in smem; flat coalesced epilogue.
__global__ __launch_bounds__(512) void roipool_kernel(const float* __restrict__ rois,
                                                      float* __restrict__ out) {
    int k   = blockIdx.x;
    int tid = threadIdx.x;

    __shared__ float rowmax[WW * CC];          // [w - ws0][c], 25.6 KB
    __shared__ float acc[CC * PH * PW];        // [c][ph*7+pw], 25.1 KB

    const float* r = rois + k * 5;
    int b  = (int)__ldg(r + 0);
    int x1 = (int)rintf(__ldg(r + 1) * SCALE);
    int y1 = (int)rintf(__ldg(r + 2) * SCALE);
    int x2 = (int)rintf(__ldg(r + 3) * SCALE);
    int y2 = (int)rintf(__ldg(r + 4) * SCALE);

    int roi_wi = max(x2 - x1 + 1, 1);
    int roi_hi = max(y2 - y1 + 1, 1);
    float bw = (float)roi_wi * (1.0f / PW);
    float bh = (float)roi_hi * (1.0f / PH);

    // w band covering all pw bins (same formulas as the bins themselves)
    int ws0 = min(max(x1, 0), WW);
    int we6 = min(max((int)ceilf((float)PW * bw) + x1, 0), WW);
    int cnt = we6 - ws0;

    int wc   = tid >> 5;   // 0..15
    int lane = tid & 31;
    const float4* fb = reinterpret_cast<const float4*>(
        g_featT + ((long)b * HH * WW) * CC) + lane;

    // per-thread pw/cp for phase 2 (tid < 224)
    int pw2 = tid >> 5;    // reuse wc: 0..15, valid when < 7
    int cp2 = lane;

    for (int ph = 0; ph < PH; ph++) {
        int hs = min(max((int)floorf((float)ph * bh) + y1, 0), HH);
        int he = min(max((int)ceilf((float)(ph + 1) * bh) + y1, 0), HH);

        // ---- Phase 1: h-reduce each w column of the band into rowmax ----
        if (he > hs) {
            for (int w = wc; w < cnt; w += 16) {
                const float4* col = fb + (long)(ws0 + w) * (CC / 4);
                float4 m = make_float4(-FLT_MAX, -FLT_MAX, -FLT_MAX, -FLT_MAX);
                int h = hs;
                for (; h + 1 < he; h += 2) {
                    float4 a  = __ldg(col + (long)(h * WW) * (CC / 4));
                    float4 b4 = __ldg(col + (long)((h + 1) * WW) * (CC / 4));
                    m = fmax4(m, fmax4(a, b4));
                }
                if (h < he) {
                    float4 a = __ldg(col + (long)(h * WW) * (CC / 4));
                    m = fmax4(m, a);
                }
                reinterpret_cast<float4*>(rowmax + w * CC)[lane] = m;
            }
        }
        __syncthreads();

        // ---- Phase 2: w-reduce per pw bin; store into acc[c][ph*7+pw] ----
        if (pw2 < PW) {
            int pw = pw2;
            int ws = min(max((int)floorf((float)pw * bw) + x1, 0), WW);
            int we = min(max((int)ceilf((float)(pw + 1) * bw) + x1, 0), WW);
            bool empty = (he <= hs) || (we <= ws);

            float4 m = make_float4(-FLT_MAX, -FLT_MAX, -FLT_MAX, -FLT_MAX);
            if (!empty) {
                for (int w = ws; w < we; w++) {
                    float4 v = reinterpret_cast<const float4*>(
                        rowmax + (w - ws0) * CC)[cp2];
                    m = fmax4(m, v);
                }
            } else {
                m = make_float4(0.f, 0.f, 0.f, 0.f);
            }
            int c = cp2 * 4;
            int o = ph * PW + pw;
            acc[(c + 0) * (PH * PW) + o] = m.x;
            acc[(c + 1) * (PH * PW) + o] = m.y;
            acc[(c + 2) * (PH * PW) + o] = m.z;
            acc[(c + 3) * (PH * PW) + o] = m.w;
        }
        __syncthreads();   // also protects rowmax before next ph overwrites it
    }

    // ---- flat coalesced epilogue: 6272 floats = 1568 float4 ----
    float4* dst = reinterpret_cast<float4*>(out + (long)k * (CC * PH * PW));
    const float4* srcv = reinterpret_cast<const float4*>(acc);
    #pragma unroll
    for (int i = 0; i < 3; i++) {
        int e = tid + i * 512;
        dst[e] = srcv[e];
    }
    {
        int e = tid + 3 * 512;
        if (e < CC * PH * PW / 4) dst[e] = srcv[e];
    }
}

extern "C" void kernel_launch(void* const* d_in, const int* in_sizes, int n_in,
                              void* d_out, int out_size) {
    const float* feat = (const float*)d_in[0];
    const float* rois = (const float*)d_in[1];
    float* out = (float*)d_out;
    int K = in_sizes[1] / 5;  // 256

    static bool attr_done = false;
    if (!attr_done) {
        cudaFuncSetAttribute(roipool_kernel,
                             cudaFuncAttributePreferredSharedMemoryCarveout, 100);
        attr_done = true;
    }

    transpose_kernel<<<NN * HH * 2, 256>>>(feat);
    roipool_kernel<<<K, 512>>>(rois, out);
}